// round 12
// baseline (speedup 1.0000x reference)
#include <cuda_runtime.h>
#include <cuda_bf16.h>
#include <math.h>
#include <stdint.h>

#define SEQN 512
#define BATN 64
#define KIN  1024
#define HN   1024
#define STEP_ELEMS (BATN * HN)          // 65536 floats per timestep

// ---------------- static scratch (device globals; no allocs) ----------------
__device__ unsigned short g_xh[SEQN * BATN * KIN];   // bf16 hi of X
__device__ unsigned short g_xl[SEQN * BATN * KIN];   // bf16 lo of X
__device__ unsigned short g_wh[HN * KIN];            // bf16 hi of W_ih
__device__ unsigned short g_wl[HN * KIN];            // bf16 lo of W_ih

// Recurrence: bf16 hi/lo of current h (one timestep, rewritten every step)
__device__ unsigned short g_hh[STEP_ELEMS];
__device__ unsigned short g_hl[STEP_ELEMS];

// Recurrence split-K partial buffer: [8][BATN][HN] = 2 MB
#define NBLK 128
#define R_KSPL 8
#define R_K    128                      // k-range per block
#define R_NS   64                       // n-cols per block
#define RSTR   136                      // padded smem stride (K + 8)
__device__ float g_part[R_KSPL * BATN * HN];
__device__ volatile unsigned g_flags[NBLK * 32];
__device__ volatile unsigned g_sense;

// ---------------- warp-MMA helpers (plain sm_103-legal PTX) ----------------
__device__ __forceinline__ uint32_t smem_u32(const void* p) {
    uint32_t a;
    asm("{ .reg .u64 t; cvta.to.shared.u64 t, %1; cvt.u32.u64 %0, t; }"
        : "=r"(a) : "l"(p));
    return a;
}
__device__ __forceinline__ void ldm_x4(uint32_t* r, uint32_t addr) {
    asm volatile("ldmatrix.sync.aligned.m8n8.x4.shared.b16 {%0,%1,%2,%3}, [%4];"
                 : "=r"(r[0]), "=r"(r[1]), "=r"(r[2]), "=r"(r[3]) : "r"(addr));
}
__device__ __forceinline__ void mma_bf16(float* d, const uint32_t* a,
                                         uint32_t b0, uint32_t b1) {
    asm volatile("mma.sync.aligned.m16n8k16.row.col.f32.bf16.bf16.f32 "
                 "{%0,%1,%2,%3}, {%4,%5,%6,%7}, {%8,%9}, {%0,%1,%2,%3};"
                 : "+f"(d[0]), "+f"(d[1]), "+f"(d[2]), "+f"(d[3])
                 : "r"(a[0]), "r"(a[1]), "r"(a[2]), "r"(a[3]), "r"(b0), "r"(b1));
}

// ---------------------------------------------------------------------------
// fp32 -> (bf16 hi, bf16 lo) split helpers.
// ---------------------------------------------------------------------------
__device__ __forceinline__ void split4(float4 v, ushort4& h, ushort4& l) {
    __nv_bfloat16 hx = __float2bfloat16(v.x), hy = __float2bfloat16(v.y);
    __nv_bfloat16 hz = __float2bfloat16(v.z), hw = __float2bfloat16(v.w);
    h.x = __bfloat16_as_ushort(hx); h.y = __bfloat16_as_ushort(hy);
    h.z = __bfloat16_as_ushort(hz); h.w = __bfloat16_as_ushort(hw);
    l.x = __bfloat16_as_ushort(__float2bfloat16(v.x - __bfloat162float(hx)));
    l.y = __bfloat16_as_ushort(__float2bfloat16(v.y - __bfloat162float(hy)));
    l.z = __bfloat16_as_ushort(__float2bfloat16(v.z - __bfloat162float(hz)));
    l.w = __bfloat16_as_ushort(__float2bfloat16(v.w - __bfloat162float(hw)));
}
__global__ __launch_bounds__(256) void split_x_kernel(const float* __restrict__ X) {
    size_t i = (size_t)blockIdx.x * 256 + threadIdx.x;
    float4 v = ((const float4*)X)[i];
    ushort4 h, l;
    split4(v, h, l);
    ((ushort4*)g_xh)[i] = h;
    ((ushort4*)g_xl)[i] = l;
}
__global__ __launch_bounds__(256) void split_w_kernel(const float* __restrict__ W) {
    size_t i = (size_t)blockIdx.x * 256 + threadIdx.x;
    float4 v = ((const float4*)W)[i];
    ushort4 h, l;
    split4(v, h, l);
    ((ushort4*)g_wh)[i] = h;
    ((ushort4*)g_wl)[i] = l;
}

// ---------------------------------------------------------------------------
// Phase A via mma.sync bf16x3 (unchanged from round 6, PASSING).
// ---------------------------------------------------------------------------
#define TSTR 40
__global__ __launch_bounds__(256) void gemm_xproj_mma_kernel(
    const float* __restrict__ bih, const float* __restrict__ bhh,
    float* __restrict__ C)
{
    __shared__ __align__(16) unsigned short Ah[128][TSTR];
    __shared__ __align__(16) unsigned short Al[128][TSTR];
    __shared__ __align__(16) unsigned short Bh[128][TSTR];
    __shared__ __align__(16) unsigned short Bl[128][TSTR];
    __shared__ float bs[128];

    const int tid = threadIdx.x;
    const int wid = tid >> 5;
    const int lid = tid & 31;
    const int n0  = blockIdx.x * 128;
    const int m0  = blockIdx.y * 128;
    const int wm  = (wid >> 1) * 32;
    const int wn  = (wid & 1) * 64;

    if (tid < 128) bs[tid] = bih[n0 + tid] + bhh[n0 + tid];

    const int lr0 = tid >> 2;
    const int lc8 = (tid & 3) * 8;
    const int lrow = lid & 15;
    const int lcol = (lid >> 4) * 8;

    float acc[16][4];
#pragma unroll
    for (int t = 0; t < 16; t++)
#pragma unroll
        for (int e = 0; e < 4; e++) acc[t][e] = 0.0f;

    const uint32_t sAh = smem_u32(Ah), sAl = smem_u32(Al);
    const uint32_t sBh = smem_u32(Bh), sBl = smem_u32(Bl);

    for (int kc = 0; kc < KIN / 32; kc++) {
        if (kc) __syncthreads();
#pragma unroll
        for (int q = 0; q < 2; q++) {
            int row = lr0 + q * 64;
            size_t gx = (size_t)(m0 + row) * KIN + kc * 32 + lc8;
            size_t gw = (size_t)(n0 + row) * KIN + kc * 32 + lc8;
            *(uint4*)&Ah[row][lc8] = *(const uint4*)(g_xh + gx);
            *(uint4*)&Al[row][lc8] = *(const uint4*)(g_xl + gx);
            *(uint4*)&Bh[row][lc8] = *(const uint4*)(g_wh + gw);
            *(uint4*)&Bl[row][lc8] = *(const uint4*)(g_wl + gw);
        }
        __syncthreads();

#pragma unroll
        for (int ks = 0; ks < 2; ks++) {
            const int kb = ks * 16;
            uint32_t ah[2][4], al[2][4], bh[4][4], bl[4][4];
#pragma unroll
            for (int i = 0; i < 2; i++) {
                uint32_t off = (uint32_t)((wm + 16 * i + lrow) * TSTR + kb + lcol) * 2;
                ldm_x4(ah[i], sAh + off);
                ldm_x4(al[i], sAl + off);
            }
#pragma unroll
            for (int j4 = 0; j4 < 4; j4++) {
                uint32_t off = (uint32_t)((wn + 16 * j4 + lrow) * TSTR + kb + lcol) * 2;
                ldm_x4(bh[j4], sBh + off);
                ldm_x4(bl[j4], sBl + off);
            }
#pragma unroll
            for (int i = 0; i < 2; i++)
#pragma unroll
                for (int j = 0; j < 8; j++) {
                    int j4 = j >> 1, sub = j & 1;
                    float* d = acc[i * 8 + j];
                    mma_bf16(d, ah[i], bh[j4][sub], bh[j4][2 + sub]);
                    mma_bf16(d, ah[i], bl[j4][sub], bl[j4][2 + sub]);
                    mma_bf16(d, al[i], bh[j4][sub], bh[j4][2 + sub]);
                }
        }
    }

    const int er = lid >> 2;
    const int ec = (lid & 3) * 2;
#pragma unroll
    for (int i = 0; i < 2; i++)
#pragma unroll
        for (int j = 0; j < 8; j++) {
            const float* d = acc[i * 8 + j];
            int cl = wn + 8 * j + ec;
            int row = m0 + wm + 16 * i + er;
            float b0 = bs[cl], b1 = bs[cl + 1];
            float2 v0, v1;
            v0.x = d[0] + b0; v0.y = d[1] + b1;
            v1.x = d[2] + b0; v1.y = d[3] + b1;
            *(float2*)(C + (size_t)row * HN + n0 + cl) = v0;
            *(float2*)(C + (size_t)(row + 8) * HN + n0 + cl) = v1;
        }
}

// ---------------------------------------------------------------------------
// Flag-based sense-reversing grid barrier (unchanged).
// ---------------------------------------------------------------------------
__device__ __forceinline__ void gsync(unsigned& sense)
{
    const unsigned ns = sense ^ 1u;
    __syncthreads();
    if (blockIdx.x == 0) {
        if (threadIdx.x == 0) {
            __threadfence();
            g_flags[0] = ns;
        }
        if (threadIdx.x < NBLK) {
            while (g_flags[threadIdx.x * 32] != ns) { }
        }
        __syncthreads();
        if (threadIdx.x == 0) {
            __threadfence();
            g_sense = ns;
        }
        __syncthreads();
    } else {
        if (threadIdx.x == 0) {
            __threadfence();
            g_flags[blockIdx.x * 32] = ns;
            while (g_sense != ns) { }
            __threadfence();
        }
        __syncthreads();
    }
    sense = ns;
}

// ---------------------------------------------------------------------------
// Persistent recurrence kernel, HMMA bf16x3 step GEMM.
// 128 blocks = 16 N-splits x 8 K-splits; per block M=64, N=64, K=128.
// W_hh tile split to bf16 hi/lo in smem ONCE; h exchanged as bf16 hi/lo.
// Dynamic smem: Wh/Wl/Hh/Hl each [64][136] ushort = 68 KB total.
// ---------------------------------------------------------------------------
__global__ __launch_bounds__(256, 1) void rnn_recurrence_mma_kernel(
    const float* __restrict__ Whh, float* __restrict__ out)
{
    extern __shared__ __align__(16) unsigned short sm[];
    unsigned short* Wh = sm;
    unsigned short* Wl = sm + 64 * RSTR;
    unsigned short* Hh = sm + 2 * 64 * RSTR;
    unsigned short* Hl = sm + 3 * 64 * RSTR;

    const int tid = threadIdx.x;
    const int bid = blockIdx.x;
    const int ks  = bid & 7;            // 0..7   K-split
    const int ns  = bid >> 3;           // 0..15  N-split
    const int n0  = ns * R_NS;
    const int k0  = ks * R_K;
    unsigned sense = 0;

    // --- Prologue: split W_hh tile [n0..n0+64) x [k0..k0+128) to bf16 smem ---
#pragma unroll
    for (int it = 0; it < 8; it++) {
        int idx = it * 256 + tid;       // 0..2047 float4s
        int row = idx >> 5;             // 0..63 (n)
        int c4  = (idx & 31) * 4;       // 0..124 (k)
        float4 v = *(const float4*)(Whh + (size_t)(n0 + row) * KIN + k0 + c4);
        ushort4 h, l;
        split4(v, h, l);
        *(ushort4*)&Wh[row * RSTR + c4] = h;
        *(ushort4*)&Wl[row * RSTR + c4] = l;
    }

    // --- Step 0: h_0 = tanh(xp_0), also emit bf16 hi/lo ---
    if (tid < 128) {
        int fi = bid * 128 + tid;       // float4 index over 64x1024
        float4 v = ((const float4*)out)[fi];
        v.x = tanhf(v.x); v.y = tanhf(v.y); v.z = tanhf(v.z); v.w = tanhf(v.w);
        ((float4*)out)[fi] = v;
        ushort4 h, l;
        split4(v, h, l);
        ((ushort4*)g_hh)[fi] = h;
        ((ushort4*)g_hl)[fi] = l;
    }
    gsync(sense);                       // barrier #1

    const int wid  = tid >> 5;
    const int lid  = tid & 31;
    const int wm   = (wid >> 2) * 32;   // warp m offset (0, 32)
    const int wn   = (wid & 3) * 16;    // warp n offset (0,16,32,48)
    const int lrow = lid & 15;
    const int lcol = (lid >> 4) * 8;
    const int er   = lid >> 2;
    const int ec   = (lid & 3) * 2;
    const uint32_t sWh = smem_u32(Wh), sWl = smem_u32(Wl);
    const uint32_t sHh = smem_u32(Hh), sHl = smem_u32(Hl);
    float* pb = g_part + (size_t)ks * STEP_ELEMS;

    for (int s = 1; s < SEQN; s++) {
        float* outs = out + (size_t)s * STEP_ELEMS;

        // --- Stage h_{s-1} bf16 hi/lo slice [64 b][k0..k0+128) ---
#pragma unroll
        for (int it = 0; it < 4; it++) {
            int idx = it * 256 + tid;   // 0..1023 uint4s (8 bf16 each)
            int row = idx >> 4;         // 0..63
            int c8  = (idx & 15) * 8;   // 0..120
            *(uint4*)&Hh[row * RSTR + c8] =
                *(const uint4*)(g_hh + (size_t)row * HN + k0 + c8);
            *(uint4*)&Hl[row * RSTR + c8] =
                *(const uint4*)(g_hl + (size_t)row * HN + k0 + c8);
        }
        __syncthreads();

        // --- HMMA bf16x3: acc[2m][2n8] frags ---
        float acc[4][4];
#pragma unroll
        for (int t = 0; t < 4; t++)
#pragma unroll
            for (int e = 0; e < 4; e++) acc[t][e] = 0.0f;

#pragma unroll
        for (int k16 = 0; k16 < 8; k16++) {
            const int kk = k16 * 16;
            uint32_t ah[2][4], al[2][4], bh[4], bl[4];
#pragma unroll
            for (int i = 0; i < 2; i++) {
                uint32_t off = (uint32_t)((wm + 16 * i + lrow) * RSTR + kk + lcol) * 2;
                ldm_x4(ah[i], sHh + off);
                ldm_x4(al[i], sHl + off);
            }
            {
                uint32_t off = (uint32_t)((wn + lrow) * RSTR + kk + lcol) * 2;
                ldm_x4(bh, sWh + off);
                ldm_x4(bl, sWl + off);
            }
#pragma unroll
            for (int i = 0; i < 2; i++)
#pragma unroll
                for (int j = 0; j < 2; j++) {
                    float* d = acc[i * 2 + j];
                    mma_bf16(d, ah[i], bh[j], bh[2 + j]);   // hh
                    mma_bf16(d, ah[i], bl[j], bl[2 + j]);   // hl
                    mma_bf16(d, al[i], bh[j], bh[2 + j]);   // lh
                }
        }

        // --- Store partials to g_part[ks] ---
#pragma unroll
        for (int i = 0; i < 2; i++)
#pragma unroll
            for (int j = 0; j < 2; j++) {
                const float* d = acc[i * 2 + j];
                int row = wm + 16 * i + er;
                int cn  = n0 + wn + 8 * j + ec;
                float2 v0, v1;
                v0.x = d[0]; v0.y = d[1];
                v1.x = d[2]; v1.y = d[3];
                *(float2*)(pb + (size_t)row * HN + cn) = v0;
                *(float2*)(pb + (size_t)(row + 8) * HN + cn) = v1;
            }

        gsync(sense);                   // partials visible

        // --- Reduce 8 partials + xp, tanh, write h_s fp32 + bf16 hi/lo ---
        if (tid < 128) {
            int fi = bid * 128 + tid;
            float4 v = ((const float4*)outs)[fi];
#pragma unroll
            for (int kp = 0; kp < R_KSPL; kp++) {
                float4 p = ((const float4*)(g_part + (size_t)kp * STEP_ELEMS))[fi];
                v.x += p.x; v.y += p.y; v.z += p.z; v.w += p.w;
            }
            v.x = tanhf(v.x); v.y = tanhf(v.y);
            v.z = tanhf(v.z); v.w = tanhf(v.w);
            ((float4*)outs)[fi] = v;
            ushort4 h, l;
            split4(v, h, l);
            ((ushort4*)g_hh)[fi] = h;
            ((ushort4*)g_hl)[fi] = l;
        }

        // Skip final barrier: total barrier count 1 + 510*2 + 1 = 1022 (even),
        // so g_sense/g_flags return to 0 for the next graph replay.
        if (s != SEQN - 1) gsync(sense);
        else __syncthreads();
    }
}

// ---------------------------------------------------------------------------
extern "C" void kernel_launch(void* const* d_in, const int* in_sizes, int n_in,
                              void* d_out, int out_size)
{
    const float* X   = (const float*)d_in[0];   // [512, 64, 1024]
    const float* Wih = (const float*)d_in[1];   // [1024, 1024]
    const float* Whh = (const float*)d_in[2];   // [1024, 1024]
    const float* bih = (const float*)d_in[3];   // [1024]
    const float* bhh = (const float*)d_in[4];   // [1024]
    float* out = (float*)d_out;                 // [32768, 1024]

    const int rec_smem = 4 * 64 * RSTR * 2;     // 69632 bytes
    cudaFuncSetAttribute(rnn_recurrence_mma_kernel,
                         cudaFuncAttributeMaxDynamicSharedMemorySize, rec_smem);

    // Nodes 1-2: bf16 hi/lo splits of X and W_ih.
    split_x_kernel<<<(SEQN * BATN * KIN / 4) / 256, 256>>>(X);
    split_w_kernel<<<(HN * KIN / 4) / 256, 256>>>(Wih);

    // Node 3: x_proj via mma.sync bf16x3, biases fused, written into d_out.
    dim3 gA(HN / 128, (SEQN * BATN) / 128);     // (8, 256)
    gemm_xproj_mma_kernel<<<gA, 256>>>(bih, bhh, out);

    // Node 4: entire recurrence in one persistent kernel (HMMA step GEMM).
    rnn_recurrence_mma_kernel<<<NBLK, 256, rec_smem>>>(Whh, out);
}

// round 13
// speedup vs baseline: 1.0499x; 1.0499x over previous
#include <cuda_runtime.h>
#include <cuda_bf16.h>
#include <math.h>
#include <stdint.h>

#define SEQN 512
#define BATN 64
#define KIN  1024
#define HN   1024
#define STEP_ELEMS (BATN * HN)          // 65536 floats per timestep

// ---------------- static scratch (device globals; no allocs) ----------------
// Recurrence: bf16 hi/lo of current h (one timestep, rewritten every step)
__device__ unsigned short g_hh[STEP_ELEMS];
__device__ unsigned short g_hl[STEP_ELEMS];

// Recurrence split-K partial buffer: [8][BATN][HN] = 2 MB
#define NBLK 128
#define R_KSPL 8
#define R_K    128                      // k-range per block
#define R_NS   64                       // n-cols per block
#define RSTR   136                      // padded smem stride (K + 8)
__device__ float g_part[R_KSPL * BATN * HN];
__device__ volatile unsigned g_flags[NBLK * 32];
__device__ volatile unsigned g_sense;
// ns-group barrier state (16 groups of 8 blocks), 128B-strided
__device__ volatile unsigned g_gcnt[16 * 32];
__device__ volatile unsigned g_gsense[16 * 32];

// ---------------- warp-MMA helpers (plain sm_103-legal PTX) ----------------
__device__ __forceinline__ uint32_t smem_u32(const void* p) {
    uint32_t a;
    asm("{ .reg .u64 t; cvta.to.shared.u64 t, %1; cvt.u32.u64 %0, t; }"
        : "=r"(a) : "l"(p));
    return a;
}
__device__ __forceinline__ void ldm_x4(uint32_t* r, uint32_t addr) {
    asm volatile("ldmatrix.sync.aligned.m8n8.x4.shared.b16 {%0,%1,%2,%3}, [%4];"
                 : "=r"(r[0]), "=r"(r[1]), "=r"(r[2]), "=r"(r[3]) : "r"(addr));
}
__device__ __forceinline__ void mma_bf16(float* d, const uint32_t* a,
                                         uint32_t b0, uint32_t b1) {
    asm volatile("mma.sync.aligned.m16n8k16.row.col.f32.bf16.bf16.f32 "
                 "{%0,%1,%2,%3}, {%4,%5,%6,%7}, {%8,%9}, {%0,%1,%2,%3};"
                 : "+f"(d[0]), "+f"(d[1]), "+f"(d[2]), "+f"(d[3])
                 : "r"(a[0]), "r"(a[1]), "r"(a[2]), "r"(a[3]), "r"(b0), "r"(b1));
}

// fp32 -> (bf16 hi, bf16 lo) split.
__device__ __forceinline__ void split4(float4 v, ushort4& h, ushort4& l) {
    __nv_bfloat16 hx = __float2bfloat16(v.x), hy = __float2bfloat16(v.y);
    __nv_bfloat16 hz = __float2bfloat16(v.z), hw = __float2bfloat16(v.w);
    h.x = __bfloat16_as_ushort(hx); h.y = __bfloat16_as_ushort(hy);
    h.z = __bfloat16_as_ushort(hz); h.w = __bfloat16_as_ushort(hw);
    l.x = __bfloat16_as_ushort(__float2bfloat16(v.x - __bfloat162float(hx)));
    l.y = __bfloat16_as_ushort(__float2bfloat16(v.y - __bfloat162float(hy)));
    l.z = __bfloat16_as_ushort(__float2bfloat16(v.z - __bfloat162float(hz)));
    l.w = __bfloat16_as_ushort(__float2bfloat16(v.w - __bfloat162float(hw)));
}

// ---------------------------------------------------------------------------
// Phase A via mma.sync bf16x3, FUSED SPLIT + double-buffered smem.
// C[m][n] = sum_k X[m][k]*W[n][k] + bih[n]+bhh[n]
// Block 128x128, BK=32, 8 warps (4m x 2n). fp32 LDG -> reg split -> bf16 STS.
// Dynamic smem: 2 buffers x 4 arrays x [128][40] ushort = 80 KB.
// ---------------------------------------------------------------------------
#define TSTR 40
#define PA_ARR (128 * TSTR)             // ushorts per tile array
#define PA_SMEM (8 * PA_ARR * 2)        // 81920 bytes

__global__ __launch_bounds__(256) void gemm_xproj_mma_kernel(
    const float* __restrict__ X, const float* __restrict__ W,
    const float* __restrict__ bih, const float* __restrict__ bhh,
    float* __restrict__ C)
{
    extern __shared__ __align__(16) unsigned short pas[];
    __shared__ float bs[128];

    const int tid = threadIdx.x;
    const int wid = tid >> 5;
    const int lid = tid & 31;
    const int n0  = blockIdx.x * 128;
    const int m0  = blockIdx.y * 128;
    const int wm  = (wid >> 1) * 32;
    const int wn  = (wid & 1) * 64;

    if (tid < 128) bs[tid] = bih[n0 + tid] + bhh[n0 + tid];

    const int lrow = lid & 15;
    const int lcol = (lid >> 4) * 8;

    float acc[16][4];
#pragma unroll
    for (int t = 0; t < 16; t++)
#pragma unroll
        for (int e = 0; e < 4; e++) acc[t][e] = 0.0f;

    // Prologue: load + split + store k-chunk 0 into buffer 0.
    float4 av[4], bv[4];
#pragma unroll
    for (int i = 0; i < 4; i++) {
        int idx = i * 256 + tid;
        int row = idx >> 3;
        int c4  = (idx & 7) << 2;
        av[i] = *(const float4*)(X + (size_t)(m0 + row) * KIN + c4);
        bv[i] = *(const float4*)(W + (size_t)(n0 + row) * KIN + c4);
    }
#pragma unroll
    for (int i = 0; i < 4; i++) {
        int idx = i * 256 + tid;
        int row = idx >> 3;
        int c4  = (idx & 7) << 2;
        ushort4 h, l;
        split4(av[i], h, l);
        *(ushort4*)&pas[0 * PA_ARR + row * TSTR + c4] = h;
        *(ushort4*)&pas[1 * PA_ARR + row * TSTR + c4] = l;
        split4(bv[i], h, l);
        *(ushort4*)&pas[2 * PA_ARR + row * TSTR + c4] = h;
        *(ushort4*)&pas[3 * PA_ARR + row * TSTR + c4] = l;
    }
    __syncthreads();

    int cur = 0;
    for (int kc = 0; kc < KIN / 32; kc++) {
        const bool has_next = (kc + 1 < KIN / 32);
        if (has_next) {
#pragma unroll
            for (int i = 0; i < 4; i++) {
                int idx = i * 256 + tid;
                int row = idx >> 3;
                int c4  = (idx & 7) << 2;
                av[i] = *(const float4*)(X + (size_t)(m0 + row) * KIN + (kc + 1) * 32 + c4);
                bv[i] = *(const float4*)(W + (size_t)(n0 + row) * KIN + (kc + 1) * 32 + c4);
            }
        }

        // Compute on current buffer while next loads are in flight.
        unsigned short* Ahp = pas + (cur * 4 + 0) * PA_ARR;
        unsigned short* Alp = pas + (cur * 4 + 1) * PA_ARR;
        unsigned short* Bhp = pas + (cur * 4 + 2) * PA_ARR;
        unsigned short* Blp = pas + (cur * 4 + 3) * PA_ARR;
        const uint32_t sAh = smem_u32(Ahp), sAl = smem_u32(Alp);
        const uint32_t sBh = smem_u32(Bhp), sBl = smem_u32(Blp);
#pragma unroll
        for (int ks = 0; ks < 2; ks++) {
            const int kb = ks * 16;
            uint32_t ah[2][4], al[2][4], bh[4][4], bl[4][4];
#pragma unroll
            for (int i = 0; i < 2; i++) {
                uint32_t off = (uint32_t)((wm + 16 * i + lrow) * TSTR + kb + lcol) * 2;
                ldm_x4(ah[i], sAh + off);
                ldm_x4(al[i], sAl + off);
            }
#pragma unroll
            for (int j4 = 0; j4 < 4; j4++) {
                uint32_t off = (uint32_t)((wn + 16 * j4 + lrow) * TSTR + kb + lcol) * 2;
                ldm_x4(bh[j4], sBh + off);
                ldm_x4(bl[j4], sBl + off);
            }
#pragma unroll
            for (int i = 0; i < 2; i++)
#pragma unroll
                for (int j = 0; j < 8; j++) {
                    int j4 = j >> 1, sub = j & 1;
                    float* d = acc[i * 8 + j];
                    mma_bf16(d, ah[i], bh[j4][sub], bh[j4][2 + sub]);   // hh
                    mma_bf16(d, ah[i], bl[j4][sub], bl[j4][2 + sub]);   // hl
                    mma_bf16(d, al[i], bh[j4][sub], bh[j4][2 + sub]);   // lh
                }
        }

        if (has_next) {
            int nxt = cur ^ 1;
#pragma unroll
            for (int i = 0; i < 4; i++) {
                int idx = i * 256 + tid;
                int row = idx >> 3;
                int c4  = (idx & 7) << 2;
                ushort4 h, l;
                split4(av[i], h, l);
                *(ushort4*)&pas[(nxt * 4 + 0) * PA_ARR + row * TSTR + c4] = h;
                *(ushort4*)&pas[(nxt * 4 + 1) * PA_ARR + row * TSTR + c4] = l;
                split4(bv[i], h, l);
                *(ushort4*)&pas[(nxt * 4 + 2) * PA_ARR + row * TSTR + c4] = h;
                *(ushort4*)&pas[(nxt * 4 + 3) * PA_ARR + row * TSTR + c4] = l;
            }
            __syncthreads();
            cur = nxt;
        }
    }

    const int er = lid >> 2;
    const int ec = (lid & 3) * 2;
#pragma unroll
    for (int i = 0; i < 2; i++)
#pragma unroll
        for (int j = 0; j < 8; j++) {
            const float* d = acc[i * 8 + j];
            int cl = wn + 8 * j + ec;
            int row = m0 + wm + 16 * i + er;
            float b0 = bs[cl], b1 = bs[cl + 1];
            float2 v0, v1;
            v0.x = d[0] + b0; v0.y = d[1] + b1;
            v1.x = d[2] + b0; v1.y = d[3] + b1;
            *(float2*)(C + (size_t)row * HN + n0 + cl) = v0;
            *(float2*)(C + (size_t)(row + 8) * HN + n0 + cl) = v1;
        }
}

// ---------------------------------------------------------------------------
// Flag-based sense-reversing full grid barrier (unchanged, proven).
// ---------------------------------------------------------------------------
__device__ __forceinline__ void gsync(unsigned& sense)
{
    const unsigned ns = sense ^ 1u;
    __syncthreads();
    if (blockIdx.x == 0) {
        if (threadIdx.x == 0) {
            __threadfence();
            g_flags[0] = ns;
        }
        if (threadIdx.x < NBLK) {
            while (g_flags[threadIdx.x * 32] != ns) { }
        }
        __syncthreads();
        if (threadIdx.x == 0) {
            __threadfence();
            g_sense = ns;
        }
        __syncthreads();
    } else {
        if (threadIdx.x == 0) {
            __threadfence();
            g_flags[blockIdx.x * 32] = ns;
            while (g_sense != ns) { }
            __threadfence();
        }
        __syncthreads();
    }
    sense = ns;
}

// 8-block ns-group barrier (atomic counter + sense; state returns to 0 after
// an even number of uses per group).
__device__ __forceinline__ void group_sync(int grp, unsigned& gs)
{
    const unsigned ns = gs ^ 1u;
    __syncthreads();
    if (threadIdx.x == 0) {
        __threadfence();                        // release partials
        unsigned old = atomicAdd((unsigned*)&g_gcnt[grp * 32], 1u);
        if (old == 7u) {
            g_gcnt[grp * 32] = 0;
            __threadfence();
            g_gsense[grp * 32] = ns;
        } else {
            while (g_gsense[grp * 32] != ns) { }
        }
        __threadfence();                        // acquire (+ L1 inval)
    }
    __syncthreads();
    gs = ns;
}

// ---------------------------------------------------------------------------
// Persistent recurrence kernel, HMMA bf16x3 step GEMM.
// 128 blocks = 16 N-splits x 8 K-splits; per block M=64, N=64, K=128.
// Per step: stage h slice -> mma -> partials -> ns-GROUP sync (8 blocks) ->
// reduce own patch (b in [8ks,8ks+8), n in [n0,n0+64)) -> FULL gsync.
// ---------------------------------------------------------------------------
__global__ __launch_bounds__(256, 1) void rnn_recurrence_mma_kernel(
    const float* __restrict__ Whh, float* __restrict__ out)
{
    extern __shared__ __align__(16) unsigned short sm[];
    unsigned short* Wh = sm;
    unsigned short* Wl = sm + 64 * RSTR;
    unsigned short* Hh = sm + 2 * 64 * RSTR;
    unsigned short* Hl = sm + 3 * 64 * RSTR;

    const int tid = threadIdx.x;
    const int bid = blockIdx.x;
    const int ks  = bid & 7;            // 0..7   K-split
    const int nsp = bid >> 3;           // 0..15  N-split
    const int n0  = nsp * R_NS;
    const int k0  = ks * R_K;
    unsigned sense = 0;
    unsigned gs = 0;

    // --- Prologue: split W_hh tile [n0..n0+64) x [k0..k0+128) to bf16 smem ---
#pragma unroll
    for (int it = 0; it < 8; it++) {
        int idx = it * 256 + tid;       // 0..2047 float4s
        int row = idx >> 5;             // 0..63 (n)
        int c4  = (idx & 31) * 4;       // 0..124 (k)
        float4 v = *(const float4*)(Whh + (size_t)(n0 + row) * KIN + k0 + c4);
        ushort4 h, l;
        split4(v, h, l);
        *(ushort4*)&Wh[row * RSTR + c4] = h;
        *(ushort4*)&Wl[row * RSTR + c4] = l;
    }

    // Parity fillers: keep total uses even (both barrier kinds) so all sync
    // state returns to 0 for the next graph replay.
    group_sync(nsp, gs);
    gsync(sense);

    // --- Step 0: h_0 = tanh(xp_0), also emit bf16 hi/lo ---
    if (tid < 128) {
        int fi = bid * 128 + tid;       // float4 index over 64x1024
        float4 v = ((const float4*)out)[fi];
        v.x = tanhf(v.x); v.y = tanhf(v.y); v.z = tanhf(v.z); v.w = tanhf(v.w);
        ((float4*)out)[fi] = v;
        ushort4 h, l;
        split4(v, h, l);
        ((ushort4*)g_hh)[fi] = h;
        ((ushort4*)g_hl)[fi] = l;
    }
    gsync(sense);

    const int wid  = tid >> 5;
    const int lid  = tid & 31;
    const int wm   = (wid >> 2) * 32;   // warp m offset (0, 32)
    const int wn   = (wid & 3) * 16;    // warp n offset (0,16,32,48)
    const int lrow = lid & 15;
    const int lcol = (lid >> 4) * 8;
    const int er   = lid >> 2;
    const int ec   = (lid & 3) * 2;
    const uint32_t sWh = smem_u32(Wh), sWl = smem_u32(Wl);
    const uint32_t sHh = smem_u32(Hh), sHl = smem_u32(Hl);
    float* pb = g_part + (size_t)ks * STEP_ELEMS;

    // Reduce-patch mapping: 128 threads, one float4 each.
    const int rb = ks * 8 + (tid >> 4);             // batch row
    const int rn = n0 + (tid & 15) * 4;             // n column (float4)
    const size_t roff = (size_t)rb * HN + rn;

    for (int s = 1; s < SEQN; s++) {
        float* outs = out + (size_t)s * STEP_ELEMS;

        // --- Stage h_{s-1} bf16 hi/lo slice [64 b][k0..k0+128) ---
#pragma unroll
        for (int it = 0; it < 4; it++) {
            int idx = it * 256 + tid;   // 0..1023 uint4s (8 bf16 each)
            int row = idx >> 4;         // 0..63
            int c8  = (idx & 15) * 8;   // 0..120
            *(uint4*)&Hh[row * RSTR + c8] =
                *(const uint4*)(g_hh + (size_t)row * HN + k0 + c8);
            *(uint4*)&Hl[row * RSTR + c8] =
                *(const uint4*)(g_hl + (size_t)row * HN + k0 + c8);
        }
        __syncthreads();

        // --- HMMA bf16x3 ---
        float acc[4][4];
#pragma unroll
        for (int t = 0; t < 4; t++)
#pragma unroll
            for (int e = 0; e < 4; e++) acc[t][e] = 0.0f;

#pragma unroll
        for (int k16 = 0; k16 < 8; k16++) {
            const int kk = k16 * 16;
            uint32_t ah[2][4], al[2][4], bh[4], bl[4];
#pragma unroll
            for (int i = 0; i < 2; i++) {
                uint32_t off = (uint32_t)((wm + 16 * i + lrow) * RSTR + kk + lcol) * 2;
                ldm_x4(ah[i], sHh + off);
                ldm_x4(al[i], sHl + off);
            }
            {
                uint32_t off = (uint32_t)((wn + lrow) * RSTR + kk + lcol) * 2;
                ldm_x4(bh, sWh + off);
                ldm_x4(bl, sWl + off);
            }
#pragma unroll
            for (int i = 0; i < 2; i++)
#pragma unroll
                for (int j = 0; j < 2; j++) {
                    float* d = acc[i * 2 + j];
                    mma_bf16(d, ah[i], bh[j], bh[2 + j]);   // hh
                    mma_bf16(d, ah[i], bl[j], bl[2 + j]);   // hl
                    mma_bf16(d, al[i], bh[j], bh[2 + j]);   // lh
                }
        }

        // --- Store partials to g_part[ks] ---
#pragma unroll
        for (int i = 0; i < 2; i++)
#pragma unroll
            for (int j = 0; j < 2; j++) {
                const float* d = acc[i * 2 + j];
                int row = wm + 16 * i + er;
                int cn  = n0 + wn + 8 * j + ec;
                float2 v0, v1;
                v0.x = d[0]; v0.y = d[1];
                v1.x = d[2]; v1.y = d[3];
                *(float2*)(pb + (size_t)row * HN + cn) = v0;
                *(float2*)(pb + (size_t)(row + 8) * HN + cn) = v1;
            }

        // Only the 8 blocks of this ns-group produce the partials this
        // block's reduce patch needs -> cheap group barrier.
        group_sync(nsp, gs);

        // --- Reduce own patch: xp + 8 partials, tanh, write fp32 + bf16 ---
        if (tid < 128) {
            float4 v = *(const float4*)(outs + roff);
#pragma unroll
            for (int kp = 0; kp < R_KSPL; kp++) {
                float4 p = *(const float4*)(g_part + (size_t)kp * STEP_ELEMS + roff);
                v.x += p.x; v.y += p.y; v.z += p.z; v.w += p.w;
            }
            v.x = tanhf(v.x); v.y = tanhf(v.y);
            v.z = tanhf(v.z); v.w = tanhf(v.w);
            *(float4*)(outs + roff) = v;
            ushort4 h, l;
            split4(v, h, l);
            ((ushort4*)g_hh)[roff >> 2] = h;
            ((ushort4*)g_hl)[roff >> 2] = l;
        }

        // Full barrier before next stage (h fully updated by all groups).
        // Skipped on the final step; counts: full = 2 + 510 = 512 (even),
        // group = 1 + 511 = 512 (even) -> replay-safe.
        if (s != SEQN - 1) gsync(sense);
        else __syncthreads();
    }
}

// ---------------------------------------------------------------------------
extern "C" void kernel_launch(void* const* d_in, const int* in_sizes, int n_in,
                              void* d_out, int out_size)
{
    const float* X   = (const float*)d_in[0];   // [512, 64, 1024]
    const float* Wih = (const float*)d_in[1];   // [1024, 1024]
    const float* Whh = (const float*)d_in[2];   // [1024, 1024]
    const float* bih = (const float*)d_in[3];   // [1024]
    const float* bhh = (const float*)d_in[4];   // [1024]
    float* out = (float*)d_out;                 // [32768, 1024]

    const int rec_smem = 4 * 64 * RSTR * 2;     // 69632 bytes
    cudaFuncSetAttribute(rnn_recurrence_mma_kernel,
                         cudaFuncAttributeMaxDynamicSharedMemorySize, rec_smem);
    cudaFuncSetAttribute(gemm_xproj_mma_kernel,
                         cudaFuncAttributeMaxDynamicSharedMemorySize, PA_SMEM);

    // Node 1: x_proj via mma.sync bf16x3, fused fp32->bf16 split on load,
    // biases fused, written into d_out.
    dim3 gA(HN / 128, (SEQN * BATN) / 128);     // (8, 256)
    gemm_xproj_mma_kernel<<<gA, 256, PA_SMEM>>>(X, Wih, bih, bhh, out);

    // Node 2: entire recurrence in one persistent kernel (HMMA step GEMM).
    rnn_recurrence_mma_kernel<<<NBLK, 256, rec_smem>>>(Whh, out);
}

// round 14
// speedup vs baseline: 1.3113x; 1.2489x over previous
#include <cuda_runtime.h>
#include <cuda_bf16.h>
#include <math.h>
#include <stdint.h>

#define SEQN 512
#define BATN 64
#define KIN  1024
#define HN   1024
#define STEP_ELEMS (BATN * HN)          // 65536 floats per timestep

// ---------------- static scratch (device globals; no allocs) ----------------
// h in bf16 hi/lo, DOUBLE-BUFFERED by step parity (h_s lives in buffer s&1).
__device__ unsigned short g_hh2[2][STEP_ELEMS];
__device__ unsigned short g_hl2[2][STEP_ELEMS];

#define NBLK 128
#define R_KSPL 8
#define R_K    128                      // k-range per block
#define R_NS   64                       // n-cols per block
#define RSTR   136                      // padded smem stride (K + 8)
__device__ float g_part[R_KSPL * BATN * HN];   // [ks][b][n], 2 MB

// Dataflow counters (monotonic within a launch; reset to 0 at kernel end).
// g_pcnt[g]: partial-stores completed by ns-group g (8 per step)
// g_rcnt[g]: h-patch writes completed by ns-group g (8 per step; step0 = first 8)
__device__ volatile unsigned g_pcnt[16 * 32];
__device__ volatile unsigned g_rcnt[16 * 32];
__device__ volatile unsigned g_fcnt;

// ---------------- warp-MMA helpers (plain sm_103-legal PTX) ----------------
__device__ __forceinline__ uint32_t smem_u32(const void* p) {
    uint32_t a;
    asm("{ .reg .u64 t; cvta.to.shared.u64 t, %1; cvt.u32.u64 %0, t; }"
        : "=r"(a) : "l"(p));
    return a;
}
__device__ __forceinline__ void ldm_x4(uint32_t* r, uint32_t addr) {
    asm volatile("ldmatrix.sync.aligned.m8n8.x4.shared.b16 {%0,%1,%2,%3}, [%4];"
                 : "=r"(r[0]), "=r"(r[1]), "=r"(r[2]), "=r"(r[3]) : "r"(addr));
}
__device__ __forceinline__ void mma_bf16(float* d, const uint32_t* a,
                                         uint32_t b0, uint32_t b1) {
    asm volatile("mma.sync.aligned.m16n8k16.row.col.f32.bf16.bf16.f32 "
                 "{%0,%1,%2,%3}, {%4,%5,%6,%7}, {%8,%9}, {%0,%1,%2,%3};"
                 : "+f"(d[0]), "+f"(d[1]), "+f"(d[2]), "+f"(d[3])
                 : "r"(a[0]), "r"(a[1]), "r"(a[2]), "r"(a[3]), "r"(b0), "r"(b1));
}

// fp32 -> (bf16 hi, bf16 lo) split.
__device__ __forceinline__ void split4(float4 v, ushort4& h, ushort4& l) {
    __nv_bfloat16 hx = __float2bfloat16(v.x), hy = __float2bfloat16(v.y);
    __nv_bfloat16 hz = __float2bfloat16(v.z), hw = __float2bfloat16(v.w);
    h.x = __bfloat16_as_ushort(hx); h.y = __bfloat16_as_ushort(hy);
    h.z = __bfloat16_as_ushort(hz); h.w = __bfloat16_as_ushort(hw);
    l.x = __bfloat16_as_ushort(__float2bfloat16(v.x - __bfloat162float(hx)));
    l.y = __bfloat16_as_ushort(__float2bfloat16(v.y - __bfloat162float(hy)));
    l.z = __bfloat16_as_ushort(__float2bfloat16(v.z - __bfloat162float(hz)));
    l.w = __bfloat16_as_ushort(__float2bfloat16(v.w - __bfloat162float(hw)));
}

// ---------------------------------------------------------------------------
// Phase A via mma.sync bf16x3, fused split + double-buffered smem (PASSING).
// ---------------------------------------------------------------------------
#define TSTR 40
#define PA_ARR (128 * TSTR)
#define PA_SMEM (8 * PA_ARR * 2)        // 81920 bytes

__global__ __launch_bounds__(256) void gemm_xproj_mma_kernel(
    const float* __restrict__ X, const float* __restrict__ W,
    const float* __restrict__ bih, const float* __restrict__ bhh,
    float* __restrict__ C)
{
    extern __shared__ __align__(16) unsigned short pas[];
    __shared__ float bs[128];

    const int tid = threadIdx.x;
    const int wid = tid >> 5;
    const int lid = tid & 31;
    const int n0  = blockIdx.x * 128;
    const int m0  = blockIdx.y * 128;
    const int wm  = (wid >> 1) * 32;
    const int wn  = (wid & 1) * 64;

    if (tid < 128) bs[tid] = bih[n0 + tid] + bhh[n0 + tid];

    const int lrow = lid & 15;
    const int lcol = (lid >> 4) * 8;

    float acc[16][4];
#pragma unroll
    for (int t = 0; t < 16; t++)
#pragma unroll
        for (int e = 0; e < 4; e++) acc[t][e] = 0.0f;

    float4 av[4], bv[4];
#pragma unroll
    for (int i = 0; i < 4; i++) {
        int idx = i * 256 + tid;
        int row = idx >> 3;
        int c4  = (idx & 7) << 2;
        av[i] = *(const float4*)(X + (size_t)(m0 + row) * KIN + c4);
        bv[i] = *(const float4*)(W + (size_t)(n0 + row) * KIN + c4);
    }
#pragma unroll
    for (int i = 0; i < 4; i++) {
        int idx = i * 256 + tid;
        int row = idx >> 3;
        int c4  = (idx & 7) << 2;
        ushort4 h, l;
        split4(av[i], h, l);
        *(ushort4*)&pas[0 * PA_ARR + row * TSTR + c4] = h;
        *(ushort4*)&pas[1 * PA_ARR + row * TSTR + c4] = l;
        split4(bv[i], h, l);
        *(ushort4*)&pas[2 * PA_ARR + row * TSTR + c4] = h;
        *(ushort4*)&pas[3 * PA_ARR + row * TSTR + c4] = l;
    }
    __syncthreads();

    int cur = 0;
    for (int kc = 0; kc < KIN / 32; kc++) {
        const bool has_next = (kc + 1 < KIN / 32);
        if (has_next) {
#pragma unroll
            for (int i = 0; i < 4; i++) {
                int idx = i * 256 + tid;
                int row = idx >> 3;
                int c4  = (idx & 7) << 2;
                av[i] = *(const float4*)(X + (size_t)(m0 + row) * KIN + (kc + 1) * 32 + c4);
                bv[i] = *(const float4*)(W + (size_t)(n0 + row) * KIN + (kc + 1) * 32 + c4);
            }
        }
        unsigned short* Ahp = pas + (cur * 4 + 0) * PA_ARR;
        unsigned short* Alp = pas + (cur * 4 + 1) * PA_ARR;
        unsigned short* Bhp = pas + (cur * 4 + 2) * PA_ARR;
        unsigned short* Blp = pas + (cur * 4 + 3) * PA_ARR;
        const uint32_t sAh = smem_u32(Ahp), sAl = smem_u32(Alp);
        const uint32_t sBh = smem_u32(Bhp), sBl = smem_u32(Blp);
#pragma unroll
        for (int ks = 0; ks < 2; ks++) {
            const int kb = ks * 16;
            uint32_t ah[2][4], al[2][4], bh[4][4], bl[4][4];
#pragma unroll
            for (int i = 0; i < 2; i++) {
                uint32_t off = (uint32_t)((wm + 16 * i + lrow) * TSTR + kb + lcol) * 2;
                ldm_x4(ah[i], sAh + off);
                ldm_x4(al[i], sAl + off);
            }
#pragma unroll
            for (int j4 = 0; j4 < 4; j4++) {
                uint32_t off = (uint32_t)((wn + 16 * j4 + lrow) * TSTR + kb + lcol) * 2;
                ldm_x4(bh[j4], sBh + off);
                ldm_x4(bl[j4], sBl + off);
            }
#pragma unroll
            for (int i = 0; i < 2; i++)
#pragma unroll
                for (int j = 0; j < 8; j++) {
                    int j4 = j >> 1, sub = j & 1;
                    float* d = acc[i * 8 + j];
                    mma_bf16(d, ah[i], bh[j4][sub], bh[j4][2 + sub]);
                    mma_bf16(d, ah[i], bl[j4][sub], bl[j4][2 + sub]);
                    mma_bf16(d, al[i], bh[j4][sub], bh[j4][2 + sub]);
                }
        }
        if (has_next) {
            int nxt = cur ^ 1;
#pragma unroll
            for (int i = 0; i < 4; i++) {
                int idx = i * 256 + tid;
                int row = idx >> 3;
                int c4  = (idx & 7) << 2;
                ushort4 h, l;
                split4(av[i], h, l);
                *(ushort4*)&pas[(nxt * 4 + 0) * PA_ARR + row * TSTR + c4] = h;
                *(ushort4*)&pas[(nxt * 4 + 1) * PA_ARR + row * TSTR + c4] = l;
                split4(bv[i], h, l);
                *(ushort4*)&pas[(nxt * 4 + 2) * PA_ARR + row * TSTR + c4] = h;
                *(ushort4*)&pas[(nxt * 4 + 3) * PA_ARR + row * TSTR + c4] = l;
            }
            __syncthreads();
            cur = nxt;
        }
    }

    const int er = lid >> 2;
    const int ec = (lid & 3) * 2;
#pragma unroll
    for (int i = 0; i < 2; i++)
#pragma unroll
        for (int j = 0; j < 8; j++) {
            const float* d = acc[i * 8 + j];
            int cl = wn + 8 * j + ec;
            int row = m0 + wm + 16 * i + er;
            float b0 = bs[cl], b1 = bs[cl + 1];
            float2 v0, v1;
            v0.x = d[0] + b0; v0.y = d[1] + b1;
            v1.x = d[2] + b0; v1.y = d[3] + b1;
            *(float2*)(C + (size_t)row * HN + n0 + cl) = v0;
            *(float2*)(C + (size_t)(row + 8) * HN + n0 + cl) = v1;
        }
}

// ---------------------------------------------------------------------------
// Persistent recurrence kernel: HMMA bf16x3 + DATAFLOW-COUNTER sync.
// 128 blocks = 16 N-splits x 8 K-splits; per block M=64, N=64, K=128.
// W_hh fragments live in REGISTERS (preloaded once). h double-buffered.
// Per step s (1..511), block (nsp, ks):
//   wait g_rcnt[2ks],[2ks+1],[nsp] >= 8s   (h_{s-1} ready; own partials freed)
//   stage h slice -> mma -> store partials -> g_pcnt[nsp]++
//   wait g_pcnt[nsp] >= 8s -> reduce own patch -> write h_s -> g_rcnt[nsp]++
// ---------------------------------------------------------------------------
__global__ __launch_bounds__(256, 1) void rnn_recurrence_mma_kernel(
    const float* __restrict__ Whh, float* __restrict__ out)
{
    __shared__ __align__(16) unsigned short Hh[64 * RSTR];   // 17.4 KB
    __shared__ __align__(16) unsigned short Hl[64 * RSTR];

    const int tid = threadIdx.x;
    const int bid = blockIdx.x;
    const int ks  = bid & 7;            // 0..7   K-split
    const int nsp = bid >> 3;           // 0..15  N-split (group id)
    const int n0  = nsp * R_NS;
    const int k0  = ks * R_K;

    const int wid  = tid >> 5;
    const int lid  = tid & 31;
    const int wm   = (wid >> 2) * 32;   // warp m offset (0, 32)
    const int wn   = (wid & 3) * 16;    // warp n offset (0,16,32,48)
    const int lrow = lid & 15;
    const int lcol = (lid >> 4) * 8;
    const int er   = lid >> 2;
    const int ec   = (lid & 3) * 2;
    const uint32_t sHh = smem_u32(Hh), sHl = smem_u32(Hl);

    // --- Prologue: split W_hh tile into smem, lift fragments to registers ---
#pragma unroll
    for (int it = 0; it < 8; it++) {
        int idx = it * 256 + tid;       // 0..2047 float4s
        int row = idx >> 5;             // 0..63 (n)
        int c4  = (idx & 31) * 4;       // 0..124 (k)
        float4 v = *(const float4*)(Whh + (size_t)(n0 + row) * KIN + k0 + c4);
        ushort4 h, l;
        split4(v, h, l);
        *(ushort4*)&Hh[row * RSTR + c4] = h;
        *(ushort4*)&Hl[row * RSTR + c4] = l;
    }
    __syncthreads();

    uint32_t bhr[8][4], blr[8][4];      // W frags, step-invariant
#pragma unroll
    for (int k16 = 0; k16 < 8; k16++) {
        uint32_t off = (uint32_t)((wn + lrow) * RSTR + k16 * 16 + lcol) * 2;
        ldm_x4(bhr[k16], sHh + off);
        ldm_x4(blr[k16], sHl + off);
    }
    __syncthreads();                    // W frags read before Hh/Hl reused

    // Patch mapping (reduce + step-0): 128 threads, one float4 each.
    const int rb = ks * 8 + (tid >> 4);             // batch row
    const int rn = n0 + (tid & 15) * 4;             // n column
    const size_t roff = (size_t)rb * HN + rn;

    // --- Step 0: h_0 = tanh(xp_0) into buffer 0 + fp32 out ---
    if (tid < 128) {
        float4 v = *(const float4*)(out + roff);
        v.x = tanhf(v.x); v.y = tanhf(v.y); v.z = tanhf(v.z); v.w = tanhf(v.w);
        *(float4*)(out + roff) = v;
        ushort4 h, l;
        split4(v, h, l);
        ((ushort4*)g_hh2[0])[roff >> 2] = h;
        ((ushort4*)g_hl2[0])[roff >> 2] = l;
    }
    __syncthreads();
    if (tid == 0) {
        __threadfence();
        atomicAdd((unsigned*)&g_rcnt[nsp * 32], 1u);
    }

    float* pb = g_part + (size_t)ks * STEP_ELEMS;
    const int g0 = 2 * ks, g1 = 2 * ks + 1;

    for (int s = 1; s < SEQN; s++) {
        float* outs = out + (size_t)s * STEP_ELEMS;
        const unsigned short* hb = g_hh2[(s - 1) & 1];
        const unsigned short* lb = g_hl2[(s - 1) & 1];
        const unsigned tgt = 8u * (unsigned)s;

        // --- Wait: h_{s-1} columns ready; own group's old partials consumed ---
        if (tid == 0) {
            while (g_rcnt[g0 * 32] < tgt) { }
            while (g_rcnt[g1 * 32] < tgt) { }
            while (g_rcnt[nsp * 32] < tgt) { }
            __threadfence();            // acquire + L1 invalidate
        }
        __syncthreads();

        // --- Stage h_{s-1} bf16 hi/lo slice [64 b][k0..k0+128) ---
#pragma unroll
        for (int it = 0; it < 4; it++) {
            int idx = it * 256 + tid;
            int row = idx >> 4;
            int c8  = (idx & 15) * 8;
            *(uint4*)&Hh[row * RSTR + c8] =
                *(const uint4*)(hb + (size_t)row * HN + k0 + c8);
            *(uint4*)&Hl[row * RSTR + c8] =
                *(const uint4*)(lb + (size_t)row * HN + k0 + c8);
        }
        __syncthreads();

        // --- HMMA bf16x3 (W frags in registers) ---
        float acc[4][4];
#pragma unroll
        for (int t = 0; t < 4; t++)
#pragma unroll
            for (int e = 0; e < 4; e++) acc[t][e] = 0.0f;

#pragma unroll
        for (int k16 = 0; k16 < 8; k16++) {
            const int kk = k16 * 16;
            uint32_t ah[2][4], al[2][4];
#pragma unroll
            for (int i = 0; i < 2; i++) {
                uint32_t off = (uint32_t)((wm + 16 * i + lrow) * RSTR + kk + lcol) * 2;
                ldm_x4(ah[i], sHh + off);
                ldm_x4(al[i], sHl + off);
            }
#pragma unroll
            for (int i = 0; i < 2; i++)
#pragma unroll
                for (int j = 0; j < 2; j++) {
                    float* d = acc[i * 2 + j];
                    mma_bf16(d, ah[i], bhr[k16][j], bhr[k16][2 + j]);   // hh
                    mma_bf16(d, ah[i], blr[k16][j], blr[k16][2 + j]);   // hl
                    mma_bf16(d, al[i], bhr[k16][j], bhr[k16][2 + j]);   // lh
                }
        }

        // --- Store partials, signal ---
#pragma unroll
        for (int i = 0; i < 2; i++)
#pragma unroll
            for (int j = 0; j < 2; j++) {
                const float* d = acc[i * 2 + j];
                int row = wm + 16 * i + er;
                int cn  = n0 + wn + 8 * j + ec;
                float2 v0, v1;
                v0.x = d[0]; v0.y = d[1];
                v1.x = d[2]; v1.y = d[3];
                *(float2*)(pb + (size_t)row * HN + cn) = v0;
                *(float2*)(pb + (size_t)(row + 8) * HN + cn) = v1;
            }
        __syncthreads();
        if (tid == 0) {
            __threadfence();
            atomicAdd((unsigned*)&g_pcnt[nsp * 32], 1u);
            while (g_pcnt[nsp * 32] < tgt) { }   // group partials complete
            __threadfence();
        }
        __syncthreads();

        // --- Reduce own patch: xp + 8 partials, tanh, write h_s ---
        if (tid < 128) {
            float4 v = *(const float4*)(outs + roff);
#pragma unroll
            for (int kp = 0; kp < R_KSPL; kp++) {
                float4 p = *(const float4*)(g_part + (size_t)kp * STEP_ELEMS + roff);
                v.x += p.x; v.y += p.y; v.z += p.z; v.w += p.w;
            }
            v.x = tanhf(v.x); v.y = tanhf(v.y);
            v.z = tanhf(v.z); v.w = tanhf(v.w);
            *(float4*)(outs + roff) = v;
            ushort4 h, l;
            split4(v, h, l);
            ((ushort4*)g_hh2[s & 1])[roff >> 2] = h;
            ((ushort4*)g_hl2[s & 1])[roff >> 2] = l;
        }
        __syncthreads();
        if (tid == 0) {
            __threadfence();
            atomicAdd((unsigned*)&g_rcnt[nsp * 32], 1u);
        }
    }

    // --- Epilogue: join + counter reset (replay safety) ---
    if (tid == 0) {
        __threadfence();
        atomicAdd((unsigned*)&g_fcnt, 1u);
        if (bid == 0) {
            while (g_fcnt < (unsigned)NBLK) { }
            for (int g = 0; g < 16; g++) {
                g_pcnt[g * 32] = 0;
                g_rcnt[g * 32] = 0;
            }
            g_fcnt = 0;
            __threadfence();
        }
    }
}

// ---------------------------------------------------------------------------
extern "C" void kernel_launch(void* const* d_in, const int* in_sizes, int n_in,
                              void* d_out, int out_size)
{
    const float* X   = (const float*)d_in[0];   // [512, 64, 1024]
    const float* Wih = (const float*)d_in[1];   // [1024, 1024]
    const float* Whh = (const float*)d_in[2];   // [1024, 1024]
    const float* bih = (const float*)d_in[3];   // [1024]
    const float* bhh = (const float*)d_in[4];   // [1024]
    float* out = (float*)d_out;                 // [32768, 1024]

    cudaFuncSetAttribute(gemm_xproj_mma_kernel,
                         cudaFuncAttributeMaxDynamicSharedMemorySize, PA_SMEM);

    // Node 1: x_proj via mma.sync bf16x3 (fused split), biases fused.
    dim3 gA(HN / 128, (SEQN * BATN) / 128);     // (8, 256)
    gemm_xproj_mma_kernel<<<gA, 256, PA_SMEM>>>(X, Wih, bih, bhh, out);

    // Node 2: entire recurrence, dataflow-counter synchronized.
    rnn_recurrence_mma_kernel<<<NBLK, 256>>>(Whh, out);
}

// round 16
// speedup vs baseline: 1.3913x; 1.0611x over previous
#include <cuda_runtime.h>
#include <cuda_bf16.h>
#include <math.h>
#include <stdint.h>

#define SEQN 512
#define BATN 64
#define KIN  1024
#define HN   1024
#define STEP_ELEMS (BATN * HN)          // 65536 floats per timestep

// ---------------- static scratch (device globals; no allocs) ----------------
// h in bf16 hi/lo, DOUBLE-BUFFERED by step parity (h_s lives in buffer s&1).
__device__ unsigned short g_hh2[2][STEP_ELEMS];
__device__ unsigned short g_hl2[2][STEP_ELEMS];
// bf16 hi/lo of W_ih (pre-split once; reused by 256 m-tiles in Phase A)
__device__ unsigned short g_wh[HN * KIN];
__device__ unsigned short g_wl[HN * KIN];

#define NBLK 128
#define R_KSPL 8
#define R_K    128                      // k-range per block
#define R_NS   64                       // n-cols per block
#define RSTR   136                      // padded smem stride (K + 8)
__device__ float g_part[R_KSPL * BATN * HN];   // [ks][b][n], 2 MB

// Dataflow counters (monotonic within a launch; reset at kernel end).
__device__ volatile unsigned g_pcnt[16 * 32];
__device__ volatile unsigned g_rcnt[16 * 32];
__device__ volatile unsigned g_fcnt;

// ---------------- warp-MMA / async-copy helpers (plain sm_103 PTX) ----------
__device__ __forceinline__ uint32_t smem_u32(const void* p) {
    uint32_t a;
    asm("{ .reg .u64 t; cvta.to.shared.u64 t, %1; cvt.u32.u64 %0, t; }"
        : "=r"(a) : "l"(p));
    return a;
}
__device__ __forceinline__ void ldm_x4(uint32_t* r, uint32_t addr) {
    asm volatile("ldmatrix.sync.aligned.m8n8.x4.shared.b16 {%0,%1,%2,%3}, [%4];"
                 : "=r"(r[0]), "=r"(r[1]), "=r"(r[2]), "=r"(r[3]) : "r"(addr));
}
__device__ __forceinline__ void mma_bf16(float* d, const uint32_t* a,
                                         uint32_t b0, uint32_t b1) {
    asm volatile("mma.sync.aligned.m16n8k16.row.col.f32.bf16.bf16.f32 "
                 "{%0,%1,%2,%3}, {%4,%5,%6,%7}, {%8,%9}, {%0,%1,%2,%3};"
                 : "+f"(d[0]), "+f"(d[1]), "+f"(d[2]), "+f"(d[3])
                 : "r"(a[0]), "r"(a[1]), "r"(a[2]), "r"(a[3]), "r"(b0), "r"(b1));
}
#define CP_ASYNC16(saddr, gptr) \
    asm volatile("cp.async.cg.shared.global [%0], [%1], 16;" \
                 :: "r"(saddr), "l"(gptr) : "memory")
#define CP_COMMIT() asm volatile("cp.async.commit_group;" ::: "memory")
#define CP_WAIT0()  asm volatile("cp.async.wait_group 0;" ::: "memory")

// fp32 -> (bf16 hi, bf16 lo) split.
__device__ __forceinline__ void split4(float4 v, ushort4& h, ushort4& l) {
    __nv_bfloat16 hx = __float2bfloat16(v.x), hy = __float2bfloat16(v.y);
    __nv_bfloat16 hz = __float2bfloat16(v.z), hw = __float2bfloat16(v.w);
    h.x = __bfloat16_as_ushort(hx); h.y = __bfloat16_as_ushort(hy);
    h.z = __bfloat16_as_ushort(hz); h.w = __bfloat16_as_ushort(hw);
    l.x = __bfloat16_as_ushort(__float2bfloat16(v.x - __bfloat162float(hx)));
    l.y = __bfloat16_as_ushort(__float2bfloat16(v.y - __bfloat162float(hy)));
    l.z = __bfloat16_as_ushort(__float2bfloat16(v.z - __bfloat162float(hz)));
    l.w = __bfloat16_as_ushort(__float2bfloat16(v.w - __bfloat162float(hw)));
}

__global__ __launch_bounds__(256) void split_w_kernel(const float* __restrict__ W) {
    size_t i = (size_t)blockIdx.x * 256 + threadIdx.x;   // float4 index
    float4 v = ((const float4*)W)[i];
    ushort4 h, l;
    split4(v, h, l);
    ((ushort4*)g_wh)[i] = h;
    ((ushort4*)g_wl)[i] = l;
}

// ---------------------------------------------------------------------------
// Phase A via mma.sync bf16x3: X fused-split on load (LDG+regs), W pre-split
// bf16 staged via cp.async. Block 128x128, BK=32, 8 warps, 2-stage smem.
// ---------------------------------------------------------------------------
#define TSTR 40
#define PA_ARR (128 * TSTR)
#define PA_SMEM (8 * PA_ARR * 2)        // 81920 bytes

__global__ __launch_bounds__(256) void gemm_xproj_mma_kernel(
    const float* __restrict__ X,
    const float* __restrict__ bih, const float* __restrict__ bhh,
    float* __restrict__ C)
{
    extern __shared__ __align__(16) unsigned short pas[];
    __shared__ float bs[128];

    const int tid = threadIdx.x;
    const int wid = tid >> 5;
    const int lid = tid & 31;
    const int n0  = blockIdx.x * 128;
    const int m0  = blockIdx.y * 128;
    const int wm  = (wid >> 1) * 32;
    const int wn  = (wid & 1) * 64;

    if (tid < 128) bs[tid] = bih[n0 + tid] + bhh[n0 + tid];

    const int lrow = lid & 15;
    const int lcol = (lid >> 4) * 8;
    const uint32_t spas = smem_u32(pas);

    float acc[16][4];
#pragma unroll
    for (int t = 0; t < 16; t++)
#pragma unroll
        for (int e = 0; e < 4; e++) acc[t][e] = 0.0f;

    float4 av[4];

    // W staging via cp.async: 4 chunks/thread (hi+lo, 128 rows x 32 bf16).
    auto stage_w = [&](int buf, int kc) {
#pragma unroll
        for (int i = 0; i < 4; i++) {
            int idx = i * 256 + tid;          // 0..1023
            int arr = idx >> 9;               // 0 = hi, 1 = lo
            int rem = idx & 511;
            int row = rem >> 2;               // 0..127
            int c8  = (rem & 3) << 3;         // 0,8,16,24
            const unsigned short* src =
                (arr ? g_wl : g_wh) + (size_t)(n0 + row) * KIN + kc * 32 + c8;
            uint32_t dst = spas +
                (uint32_t)(((buf * 4 + 2 + arr) * PA_ARR + row * TSTR + c8) * 2);
            CP_ASYNC16(dst, src);
        }
    };

    // Prologue: k-chunk 0 into buffer 0.
    stage_w(0, 0);
    CP_COMMIT();
#pragma unroll
    for (int i = 0; i < 4; i++) {
        int idx = i * 256 + tid;
        int row = idx >> 3, c4 = (idx & 7) << 2;
        av[i] = *(const float4*)(X + (size_t)(m0 + row) * KIN + c4);
    }
#pragma unroll
    for (int i = 0; i < 4; i++) {
        int idx = i * 256 + tid;
        int row = idx >> 3, c4 = (idx & 7) << 2;
        ushort4 h, l;
        split4(av[i], h, l);
        *(ushort4*)&pas[0 * PA_ARR + row * TSTR + c4] = h;
        *(ushort4*)&pas[1 * PA_ARR + row * TSTR + c4] = l;
    }
    CP_WAIT0();
    __syncthreads();

    int cur = 0;
    for (int kc = 0; kc < KIN / 32; kc++) {
        const bool has_next = (kc + 1 < KIN / 32);
        if (has_next) {
            stage_w(cur ^ 1, kc + 1);         // async into next buffer
            CP_COMMIT();
#pragma unroll
            for (int i = 0; i < 4; i++) {
                int idx = i * 256 + tid;
                int row = idx >> 3, c4 = (idx & 7) << 2;
                av[i] = *(const float4*)(X + (size_t)(m0 + row) * KIN + (kc + 1) * 32 + c4);
            }
        }
        const uint32_t sAh = spas + (uint32_t)((cur * 4 + 0) * PA_ARR) * 2;
        const uint32_t sAl = spas + (uint32_t)((cur * 4 + 1) * PA_ARR) * 2;
        const uint32_t sBh = spas + (uint32_t)((cur * 4 + 2) * PA_ARR) * 2;
        const uint32_t sBl = spas + (uint32_t)((cur * 4 + 3) * PA_ARR) * 2;
#pragma unroll
        for (int ks = 0; ks < 2; ks++) {
            const int kb = ks * 16;
            uint32_t ah[2][4], al[2][4], bh[4][4], bl[4][4];
#pragma unroll
            for (int i = 0; i < 2; i++) {
                uint32_t off = (uint32_t)((wm + 16 * i + lrow) * TSTR + kb + lcol) * 2;
                ldm_x4(ah[i], sAh + off);
                ldm_x4(al[i], sAl + off);
            }
#pragma unroll
            for (int j4 = 0; j4 < 4; j4++) {
                uint32_t off = (uint32_t)((wn + 16 * j4 + lrow) * TSTR + kb + lcol) * 2;
                ldm_x4(bh[j4], sBh + off);
                ldm_x4(bl[j4], sBl + off);
            }
#pragma unroll
            for (int i = 0; i < 2; i++)
#pragma unroll
                for (int j = 0; j < 8; j++) {
                    int j4 = j >> 1, sub = j & 1;
                    float* d = acc[i * 8 + j];
                    mma_bf16(d, ah[i], bh[j4][sub], bh[j4][2 + sub]);
                    mma_bf16(d, ah[i], bl[j4][sub], bl[j4][2 + sub]);
                    mma_bf16(d, al[i], bh[j4][sub], bh[j4][2 + sub]);
                }
        }
        if (has_next) {
            int nxt = cur ^ 1;
#pragma unroll
            for (int i = 0; i < 4; i++) {
                int idx = i * 256 + tid;
                int row = idx >> 3, c4 = (idx & 7) << 2;
                ushort4 h, l;
                split4(av[i], h, l);
                *(ushort4*)&pas[(nxt * 4 + 0) * PA_ARR + row * TSTR + c4] = h;
                *(ushort4*)&pas[(nxt * 4 + 1) * PA_ARR + row * TSTR + c4] = l;
            }
            CP_WAIT0();
            __syncthreads();
            cur = nxt;
        }
    }

    const int er = lid >> 2;
    const int ec = (lid & 3) * 2;
#pragma unroll
    for (int i = 0; i < 2; i++)
#pragma unroll
        for (int j = 0; j < 8; j++) {
            const float* d = acc[i * 8 + j];
            int cl = wn + 8 * j + ec;
            int row = m0 + wm + 16 * i + er;
            float b0 = bs[cl], b1 = bs[cl + 1];
            float2 v0, v1;
            v0.x = d[0] + b0; v0.y = d[1] + b1;
            v1.x = d[2] + b0; v1.y = d[3] + b1;
            *(float2*)(C + (size_t)row * HN + n0 + cl) = v0;
            *(float2*)(C + (size_t)(row + 8) * HN + n0 + cl) = v1;
        }
}

// ---------------------------------------------------------------------------
// Persistent recurrence: HMMA bf16x3 + dataflow counters (round-14 proven
// structure; NO clusters). Adds: parallel counter polls, xp prefetch,
// cp.async h staging.
// ---------------------------------------------------------------------------
__global__ __launch_bounds__(256, 1) void rnn_recurrence_mma_kernel(
    const float* __restrict__ Whh, float* __restrict__ out)
{
    __shared__ __align__(16) unsigned short Hh[64 * RSTR];   // 17.4 KB
    __shared__ __align__(16) unsigned short Hl[64 * RSTR];

    const int tid = threadIdx.x;
    const int bid = blockIdx.x;
    const int ks  = bid & 7;            // 0..7   K-split
    const int nsp = bid >> 3;           // 0..15  N-split (group id)
    const int n0  = nsp * R_NS;
    const int k0  = ks * R_K;

    const int wid  = tid >> 5;
    const int lid  = tid & 31;
    const int wm   = (wid >> 2) * 32;
    const int wn   = (wid & 3) * 16;
    const int lrow = lid & 15;
    const int lcol = (lid >> 4) * 8;
    const int er   = lid >> 2;
    const int ec   = (lid & 3) * 2;
    const uint32_t sHh = smem_u32(Hh), sHl = smem_u32(Hl);

    // --- Prologue: split W_hh tile into smem, lift fragments to registers ---
#pragma unroll
    for (int it = 0; it < 8; it++) {
        int idx = it * 256 + tid;
        int row = idx >> 5;
        int c4  = (idx & 31) * 4;
        float4 v = *(const float4*)(Whh + (size_t)(n0 + row) * KIN + k0 + c4);
        ushort4 h, l;
        split4(v, h, l);
        *(ushort4*)&Hh[row * RSTR + c4] = h;
        *(ushort4*)&Hl[row * RSTR + c4] = l;
    }
    __syncthreads();

    uint32_t bhr[8][4], blr[8][4];      // W frags, step-invariant
#pragma unroll
    for (int k16 = 0; k16 < 8; k16++) {
        uint32_t off = (uint32_t)((wn + lrow) * RSTR + k16 * 16 + lcol) * 2;
        ldm_x4(bhr[k16], sHh + off);
        ldm_x4(blr[k16], sHl + off);
    }
    __syncthreads();                    // W frags read before Hh/Hl reused

    // Patch mapping (reduce + step-0): 128 threads, one float4 each.
    const int rb = ks * 8 + (tid >> 4);             // batch row
    const int rn = n0 + (tid & 15) * 4;             // n column
    const size_t roff = (size_t)rb * HN + rn;

    // --- Step 0: h_0 = tanh(xp_0) into buffer 0 + fp32 out ---
    if (tid < 128) {
        float4 v = *(const float4*)(out + roff);
        v.x = tanhf(v.x); v.y = tanhf(v.y); v.z = tanhf(v.z); v.w = tanhf(v.w);
        *(float4*)(out + roff) = v;
        ushort4 h, l;
        split4(v, h, l);
        ((ushort4*)g_hh2[0])[roff >> 2] = h;
        ((ushort4*)g_hl2[0])[roff >> 2] = l;
    }
    __syncthreads();
    if (tid == 0) {
        __threadfence();
        atomicAdd((unsigned*)&g_rcnt[nsp * 32], 1u);
    }

    float* pb = g_part + (size_t)ks * STEP_ELEMS;
    const int g0 = 2 * ks, g1 = 2 * ks + 1;

    for (int s = 1; s < SEQN; s++) {
        float* outs = out + (size_t)s * STEP_ELEMS;
        const unsigned short* hb = g_hh2[(s - 1) & 1];
        const unsigned short* lb = g_hl2[(s - 1) & 1];
        const unsigned tgt = 8u * (unsigned)s;

        // --- Parallel wait on the 3 producer counters ---
        if (tid < 3) {
            int g = (tid == 0) ? g0 : (tid == 1) ? g1 : nsp;
            while (g_rcnt[g * 32] < tgt) { }
        }
        __syncthreads();
        if (tid == 0) __threadfence();  // acquire; flushes SM L1
        __syncthreads();

        // --- Prefetch xp (hides under stage + mma) ---
        float4 xp;
        if (tid < 128) xp = *(const float4*)(outs + roff);

        // --- Stage h_{s-1} bf16 hi/lo slice via cp.async (L2-direct) ---
#pragma unroll
        for (int it = 0; it < 8; it++) {
            int idx = it * 256 + tid;   // 0..2047 16B-chunks
            int arr = idx >> 10;        // 0 = hi, 1 = lo
            int rem = idx & 1023;
            int row = rem >> 4;         // 0..63
            int c8  = (rem & 15) << 3;  // 0..120
            const unsigned short* src =
                (arr ? lb : hb) + (size_t)row * HN + k0 + c8;
            uint32_t dst = (arr ? sHl : sHh) + (uint32_t)(row * RSTR + c8) * 2;
            CP_ASYNC16(dst, src);
        }
        CP_COMMIT();
        CP_WAIT0();
        __syncthreads();

        // --- HMMA bf16x3 (W frags in registers) ---
        float acc[4][4];
#pragma unroll
        for (int t = 0; t < 4; t++)
#pragma unroll
            for (int e = 0; e < 4; e++) acc[t][e] = 0.0f;

#pragma unroll
        for (int k16 = 0; k16 < 8; k16++) {
            const int kk = k16 * 16;
            uint32_t ah[2][4], al[2][4];
#pragma unroll
            for (int i = 0; i < 2; i++) {
                uint32_t off = (uint32_t)((wm + 16 * i + lrow) * RSTR + kk + lcol) * 2;
                ldm_x4(ah[i], sHh + off);
                ldm_x4(al[i], sHl + off);
            }
#pragma unroll
            for (int i = 0; i < 2; i++)
#pragma unroll
                for (int j = 0; j < 2; j++) {
                    float* d = acc[i * 2 + j];
                    mma_bf16(d, ah[i], bhr[k16][j], bhr[k16][2 + j]);   // hh
                    mma_bf16(d, ah[i], blr[k16][j], blr[k16][2 + j]);   // hl
                    mma_bf16(d, al[i], bhr[k16][j], bhr[k16][2 + j]);   // lh
                }
        }

        // --- Store partials, signal ---
#pragma unroll
        for (int i = 0; i < 2; i++)
#pragma unroll
            for (int j = 0; j < 2; j++) {
                const float* d = acc[i * 2 + j];
                int row = wm + 16 * i + er;
                int cn  = n0 + wn + 8 * j + ec;
                float2 v0, v1;
                v0.x = d[0]; v0.y = d[1];
                v1.x = d[2]; v1.y = d[3];
                *(float2*)(pb + (size_t)row * HN + cn) = v0;
                *(float2*)(pb + (size_t)(row + 8) * HN + cn) = v1;
            }
        __syncthreads();
        if (tid == 0) {
            __threadfence();
            atomicAdd((unsigned*)&g_pcnt[nsp * 32], 1u);
            while (g_pcnt[nsp * 32] < tgt) { }   // group partials complete
            __threadfence();
        }
        __syncthreads();

        // --- Reduce own patch: xp + 8 partials, tanh, write h_s ---
        if (tid < 128) {
            float4 v = xp;
#pragma unroll
            for (int kp = 0; kp < R_KSPL; kp++) {
                float4 p = *(const float4*)(g_part + (size_t)kp * STEP_ELEMS + roff);
                v.x += p.x; v.y += p.y; v.z += p.z; v.w += p.w;
            }
            v.x = tanhf(v.x); v.y = tanhf(v.y);
            v.z = tanhf(v.z); v.w = tanhf(v.w);
            *(float4*)(outs + roff) = v;
            ushort4 h, l;
            split4(v, h, l);
            ((ushort4*)g_hh2[s & 1])[roff >> 2] = h;
            ((ushort4*)g_hl2[s & 1])[roff >> 2] = l;
        }
        __syncthreads();
        if (tid == 0) {
            __threadfence();
            atomicAdd((unsigned*)&g_rcnt[nsp * 32], 1u);
        }
    }

    // --- Epilogue: join + counter reset (replay safety) ---
    if (tid == 0) {
        __threadfence();
        atomicAdd((unsigned*)&g_fcnt, 1u);
        if (bid == 0) {
            while (g_fcnt < (unsigned)NBLK) { }
            for (int g = 0; g < 16; g++) {
                g_pcnt[g * 32] = 0;
                g_rcnt[g * 32] = 0;
            }
            g_fcnt = 0;
            __threadfence();
        }
    }
}

// ---------------------------------------------------------------------------
extern "C" void kernel_launch(void* const* d_in, const int* in_sizes, int n_in,
                              void* d_out, int out_size)
{
    const float* X   = (const float*)d_in[0];   // [512, 64, 1024]
    const float* Wih = (const float*)d_in[1];   // [1024, 1024]
    const float* Whh = (const float*)d_in[2];   // [1024, 1024]
    const float* bih = (const float*)d_in[3];   // [1024]
    const float* bhh = (const float*)d_in[4];   // [1024]
    float* out = (float*)d_out;                 // [32768, 1024]

    cudaFuncSetAttribute(gemm_xproj_mma_kernel,
                         cudaFuncAttributeMaxDynamicSharedMemorySize, PA_SMEM);

    // Node 1: pre-split W_ih to bf16 hi/lo (enables cp.async W staging).
    split_w_kernel<<<(HN * KIN / 4) / 256, 256>>>(Wih);

    // Node 2: x_proj via mma.sync bf16x3, biases fused, into d_out.
    dim3 gA(HN / 128, (SEQN * BATN) / 128);     // (8, 256)
    gemm_xproj_mma_kernel<<<gA, 256, PA_SMEM>>>(X, bih, bhh, out);

    // Node 3: entire recurrence, dataflow-counter synchronized (no clusters).
    rnn_recurrence_mma_kernel<<<NBLK, 256>>>(Whh, out);
}